// round 6
// baseline (speedup 1.0000x reference)
#include <cuda_runtime.h>
#include <cstdint>

#define NV 778
#define NF 1538
#define NB 4
#define OW 128
#define OH 128
#define BGD 1e10f
#define NSLICE 32
#define CHUNK ((NF + NSLICE - 1) / NSLICE)        // 49
#define NROUND ((CHUNK + 31) / 32)                // 2

// Per-slice partial z-buffers (uint bits of positive floats; order-preserving).
// Layout: [slice][b][row][col]. 32*4*128*128*4B = 8 MB.
__device__ unsigned int g_part[NSLICE * NB * OH * OW];

// Fused kernel: per-CTA face setup (smem, SoA) + ballot-compacted, fully
// branchless raster of one 32x32 output tile per (batch, face-slice).
__global__ void __launch_bounds__(256) raster_kernel(
    const float* __restrict__ verts, const int* __restrict__ faces)
{
    __shared__ float4 sbb[CHUNK];          // (xmin, xmax, ymin, ymax)
    __shared__ float4 sed[CHUNK * 4];      // e0,e1,e2,w per face
    //   e: (s*dx, s*dy, refx, refy)  ->  e' = s*dx*(py-refy) - s*dy*(px-refx)
    //   w: (z0/|area|, z1/|area|, z2/|area|, 0)

    int bz = blockIdx.z;
    int b = bz >> 5;           // NSLICE == 32
    int slice = bz & 31;
    int f0 = slice * CHUNK;
    int nf = min(NF - f0, CHUNK);

    // ---- Phase 1: build this chunk's face records in smem ----
    int t = threadIdx.x;
    if (t < nf) {
        int f = f0 + t;
        // faces land on device as int32 (JAX x64 disabled). Clamp defensively.
        int i0 = min(max(faces[f * 3 + 0], 0), NV - 1);
        int i1 = min(max(faces[f * 3 + 1], 0), NV - 1);
        int i2 = min(max(faces[f * 3 + 2], 0), NV - 1);
        const float* vb = verts + (size_t)b * NV * 3;
        float x0 = vb[i0 * 3 + 0], y0 = vb[i0 * 3 + 1], z0 = vb[i0 * 3 + 2];
        float x1 = vb[i1 * 3 + 0], y1 = vb[i1 * 3 + 1], z1 = vb[i1 * 3 + 2];
        float x2 = vb[i2 * 3 + 0], y2 = vb[i2 * 3 + 1], z2 = vb[i2 * 3 + 2];

        // area with reference rounding (no FMA contraction)
        float area = __fsub_rn(__fmul_rn(__fsub_rn(x1, x0), __fsub_rn(y2, y0)),
                               __fmul_rn(__fsub_rn(y1, y0), __fsub_rn(x2, x0)));
        float s = (area > 0.0f) ? 1.0f : -1.0f;
        bool valid = fabsf(area) > 1e-12f;

        float4 bb, e0, e1, e2, wv;
        if (valid) {
            float inv = 1.0f / fabsf(area);
            e0 = make_float4(s * __fsub_rn(x2, x1), s * __fsub_rn(y2, y1), x1, y1);
            e1 = make_float4(s * __fsub_rn(x0, x2), s * __fsub_rn(y0, y2), x2, y2);
            e2 = make_float4(s * __fsub_rn(x1, x0), s * __fsub_rn(y1, y0), x0, y0);
            wv = make_float4(z0 * inv, z1 * inv, z2 * inv, 0.0f);
            bb = make_float4(fminf(x0, fminf(x1, x2)), fmaxf(x0, fmaxf(x1, x2)),
                             fminf(y0, fminf(y1, y2)), fmaxf(y0, fmaxf(y1, y2)));
        } else {
            e0 = e1 = e2 = make_float4(0.0f, 1.0f, -4e9f, 0.0f);
            wv = make_float4(0.0f, 0.0f, 0.0f, 0.0f);
            bb = make_float4(3e38f, -3e38f, 3e38f, -3e38f);   // cull always
        }
        sbb[t] = bb;
        sed[t * 4 + 0] = e0;
        sed[t * 4 + 1] = e1;
        sed[t * 4 + 2] = e2;
        sed[t * 4 + 3] = wv;
    }
    __syncthreads();

    // ---- Phase 2: rasterize. Warp = 32 cols x 4 rows; thread owns a 4-pixel
    //      column. Sample coords: x = 5*col+2.5, y = 5*row+2.5 (exact fp32).
    int lane = threadIdx.x & 31;
    int w = threadIdx.x >> 5;
    int col = blockIdx.x * 32 + lane;
    int row0 = blockIdx.y * 32 + w * 4;

    float px = 5.0f * (float)col + 2.5f;
    float py0 = 5.0f * (float)row0 + 2.5f;

    // warp-uniform tile bounds with rounding margin
    float txmin = 5.0f * (float)(blockIdx.x * 32) + 2.5f - 1.0f;
    float txmax = txmin + 155.0f + 2.0f;
    float tymin = py0 - 1.0f;
    float tymax = tymin + 15.0f + 2.0f;

    // Scan: lane L tests face (r*32 + L); ballot builds the pass mask.
    unsigned int mask[NROUND];
#pragma unroll
    for (int r = 0; r < NROUND; r++) {
        int f = r * 32 + lane;
        bool pass = false;
        if (f < nf) {
            float4 bb = sbb[f];
            pass = !(bb.y < txmin || bb.x > txmax || bb.w < tymin || bb.z > tymax);
        }
        mask[r] = __ballot_sync(0xFFFFFFFFu, pass);
    }

    float zb[4] = {BGD, BGD, BGD, BGD};

#pragma unroll
    for (int r = 0; r < NROUND; r++) {
        unsigned int m = mask[r];
        while (m) {
            int i = __ffs(m) - 1;
            m &= m - 1;
            int f = r * 32 + i;

            float4 e0 = sed[f * 4 + 0];
            float4 e1 = sed[f * 4 + 1];
            float4 e2 = sed[f * 4 + 2];
            float4 wv = sed[f * 4 + 3];

            // per-column constants (x part of each edge fn), reference rounding
            float m20 = __fmul_rn(e0.y, __fsub_rn(px, e0.z));
            float m21 = __fmul_rn(e1.y, __fsub_rn(px, e1.z));
            float m22 = __fmul_rn(e2.y, __fsub_rn(px, e2.z));

            // Branchless: compute z always, select BGD when outside (FSEL),
            // fold with fminf — mirrors reference's where(inside, z, BGD).
#pragma unroll
            for (int k = 0; k < 4; k++) {
                float py = py0 + 5.0f * (float)k;   // exact
                float ea = __fsub_rn(__fmul_rn(e0.x, __fsub_rn(py, e0.w)), m20);
                float eb = __fsub_rn(__fmul_rn(e1.x, __fsub_rn(py, e1.w)), m21);
                float ec = __fsub_rn(__fmul_rn(e2.x, __fsub_rn(py, e2.w)), m22);
                float emin = fminf(ea, fminf(eb, ec));
                float z = fmaf(ea, wv.x, fmaf(eb, wv.y, __fmul_rn(ec, wv.z)));
                float cand = (emin >= 0.0f) ? z : BGD;
                zb[k] = fminf(zb[k], cand);
            }
        }
    }

    // ---- Phase 3: unconditional private-tile store (no atomics) ----
    unsigned int* base = g_part + ((size_t)(slice * NB + b) * OH) * OW;
#pragma unroll
    for (int k = 0; k < 4; k++)
        base[(size_t)(row0 + k) * OW + col] = __float_as_uint(zb[k]);
}

// Merge the 32 slice buffers, clamp, write output. One uint per thread:
// 65536 threads / 256 CTAs -> every SM busy, 32 independent loads per thread.
__global__ void __launch_bounds__(256) finalize_kernel(float* __restrict__ out)
{
    int idx = blockIdx.x * blockDim.x + threadIdx.x;
    if (idx >= NB * OH * OW) return;

    const unsigned int* p = g_part + idx;
    const int stride = NB * OH * OW;

    unsigned int acc = p[0];
#pragma unroll
    for (int s = 1; s < NSLICE; s++)
        acc = min(acc, p[(size_t)s * stride]);

    out[idx] = fminf(__uint_as_float(acc), 100.0f);
}

extern "C" void kernel_launch(void* const* d_in, const int* in_sizes, int n_in,
                              void* d_out, int out_size)
{
    const float* verts = (const float*)d_in[0];
    const int* faces = (const int*)d_in[1];
    float* out = (float*)d_out;

    dim3 grid(OW / 32, OH / 32, NB * NSLICE);   // (4, 4, 128) = 2048 CTAs
    raster_kernel<<<grid, 256>>>(verts, faces);

    finalize_kernel<<<(NB * OH * OW + 255) / 256, 256>>>(out);
}

// round 7
// speedup vs baseline: 1.0446x; 1.0446x over previous
#include <cuda_runtime.h>
#include <cstdint>

#define NV 778
#define NF 1538
#define NB 4
#define OW 128
#define OH 128
#define BGD 1e10f
#define NSLICE 32
#define CHUNK ((NF + NSLICE - 1) / NSLICE)        // 49
#define NROUND ((CHUNK + 31) / 32)                // 2
#define NPIX (NB * OH * OW)                       // 65536

// Per-slice partial z-buffers (uint bits of positive floats; order-preserving).
// Layout: [slice][b][row][col]. 32*4*128*128*4B = 8 MB.
__device__ unsigned int g_part[NSLICE * NPIX];

// Fused kernel: per-CTA face setup (smem, SoA) + ballot-compacted raster of
// one 32x32 output tile for one (batch, face-slice). No atomics.
__global__ void __launch_bounds__(256) raster_kernel(
    const float* __restrict__ verts, const int* __restrict__ faces)
{
    __shared__ float4 sbb[CHUNK];          // (xmin, xmax, ymin, ymax)
    __shared__ float4 sed[CHUNK * 4];      // e0,e1,e2,w per face
    //   e: (s*dx, s*dy, refx, refy)  ->  e' = s*dx*(py-refy) - s*dy*(px-refx)
    //   w: (z0/|area|, z1/|area|, z2/|area|, 0)

    int bz = blockIdx.z;
    int b = bz >> 5;           // NSLICE == 32
    int slice = bz & 31;
    int f0 = slice * CHUNK;
    int nf = min(NF - f0, CHUNK);

    // ---- Phase 1: build this chunk's face records in smem ----
    int t = threadIdx.x;
    if (t < nf) {
        int f = f0 + t;
        // faces land on device as int32 (JAX x64 disabled). Clamp defensively.
        int i0 = min(max(faces[f * 3 + 0], 0), NV - 1);
        int i1 = min(max(faces[f * 3 + 1], 0), NV - 1);
        int i2 = min(max(faces[f * 3 + 2], 0), NV - 1);
        const float* vb = verts + (size_t)b * NV * 3;
        float x0 = vb[i0 * 3 + 0], y0 = vb[i0 * 3 + 1], z0 = vb[i0 * 3 + 2];
        float x1 = vb[i1 * 3 + 0], y1 = vb[i1 * 3 + 1], z1 = vb[i1 * 3 + 2];
        float x2 = vb[i2 * 3 + 0], y2 = vb[i2 * 3 + 1], z2 = vb[i2 * 3 + 2];

        // area with reference rounding (no FMA contraction)
        float area = __fsub_rn(__fmul_rn(__fsub_rn(x1, x0), __fsub_rn(y2, y0)),
                               __fmul_rn(__fsub_rn(y1, y0), __fsub_rn(x2, x0)));
        float s = (area > 0.0f) ? 1.0f : -1.0f;
        bool valid = fabsf(area) > 1e-12f;

        float4 bb, e0, e1, e2, wv;
        if (valid) {
            float inv = 1.0f / fabsf(area);
            e0 = make_float4(s * __fsub_rn(x2, x1), s * __fsub_rn(y2, y1), x1, y1);
            e1 = make_float4(s * __fsub_rn(x0, x2), s * __fsub_rn(y0, y2), x2, y2);
            e2 = make_float4(s * __fsub_rn(x1, x0), s * __fsub_rn(y1, y0), x0, y0);
            wv = make_float4(z0 * inv, z1 * inv, z2 * inv, 0.0f);
            bb = make_float4(fminf(x0, fminf(x1, x2)), fmaxf(x0, fmaxf(x1, x2)),
                             fminf(y0, fminf(y1, y2)), fmaxf(y0, fmaxf(y1, y2)));
        } else {
            e0 = e1 = e2 = make_float4(0.0f, 1.0f, -4e9f, 0.0f);
            wv = make_float4(0.0f, 0.0f, 0.0f, 0.0f);
            bb = make_float4(3e38f, -3e38f, 3e38f, -3e38f);   // cull always
        }
        sbb[t] = bb;
        sed[t * 4 + 0] = e0;
        sed[t * 4 + 1] = e1;
        sed[t * 4 + 2] = e2;
        sed[t * 4 + 3] = wv;
    }
    __syncthreads();

    // ---- Phase 2: rasterize. Warp = 32 cols x 4 rows; thread owns a 4-pixel
    //      column. Sample coords: x = 5*col+2.5, y = 5*row+2.5 (exact fp32).
    int lane = threadIdx.x & 31;
    int w = threadIdx.x >> 5;
    int col = blockIdx.x * 32 + lane;
    int row0 = blockIdx.y * 32 + w * 4;

    float px = 5.0f * (float)col + 2.5f;
    float py0 = 5.0f * (float)row0 + 2.5f;

    // warp-uniform tile bounds with rounding margin
    float txmin = 5.0f * (float)(blockIdx.x * 32) + 2.5f - 1.0f;
    float txmax = txmin + 155.0f + 2.0f;
    float tymin = py0 - 1.0f;
    float tymax = tymin + 15.0f + 2.0f;

    // Scan: lane L tests face (r*32 + L); ballot builds the pass mask.
    unsigned int mask[NROUND];
#pragma unroll
    for (int r = 0; r < NROUND; r++) {
        int f = r * 32 + lane;
        bool pass = false;
        if (f < nf) {
            float4 bb = sbb[f];
            pass = !(bb.y < txmin || bb.x > txmax || bb.w < tymin || bb.z > tymax);
        }
        mask[r] = __ballot_sync(0xFFFFFFFFu, pass);
    }

    float zb[4] = {BGD, BGD, BGD, BGD};

#pragma unroll
    for (int r = 0; r < NROUND; r++) {
        unsigned int m = mask[r];
        while (m) {
            int i = __ffs(m) - 1;
            m &= m - 1;
            int f = r * 32 + i;

            float4 e0 = sed[f * 4 + 0];
            float4 e1 = sed[f * 4 + 1];
            float4 e2 = sed[f * 4 + 2];
            float4 wv = sed[f * 4 + 3];

            // per-column constants (x part of each edge fn), reference rounding
            float m20 = __fmul_rn(e0.y, __fsub_rn(px, e0.z));
            float m21 = __fmul_rn(e1.y, __fsub_rn(px, e1.z));
            float m22 = __fmul_rn(e2.y, __fsub_rn(px, e2.z));

#pragma unroll
            for (int k = 0; k < 4; k++) {
                float py = py0 + 5.0f * (float)k;   // exact
                float ea = __fsub_rn(__fmul_rn(e0.x, __fsub_rn(py, e0.w)), m20);
                float eb = __fsub_rn(__fmul_rn(e1.x, __fsub_rn(py, e1.w)), m21);
                float ec = __fsub_rn(__fmul_rn(e2.x, __fsub_rn(py, e2.w)), m22);
                if (fminf(ea, fminf(eb, ec)) >= 0.0f) {
                    // continuous path: FMA + precomputed 1/|area| is safe
                    float z = fmaf(ea, wv.x, fmaf(eb, wv.y, __fmul_rn(ec, wv.z)));
                    zb[k] = fminf(zb[k], z);
                }
            }
        }
    }

    // ---- Phase 3: unconditional private-tile store (no atomics) ----
    unsigned int* base = g_part + ((size_t)(slice * NB + b) * OH) * OW;
#pragma unroll
    for (int k = 0; k < 4; k++)
        base[(size_t)(row0 + k) * OW + col] = __float_as_uint(zb[k]);
}

// Merge the 32 slice buffers, clamp, write output.
// Occupancy fix: 4 thread-groups of 64 threads each merge 8 slices for 64
// pixels, combined through smem. 1024 CTAs -> all SMs busy.
__global__ void __launch_bounds__(256) finalize_kernel(float* __restrict__ out)
{
    __shared__ unsigned int smem[256];

    int t = threadIdx.x;
    int px = blockIdx.x * 64 + (t & 63);
    int g = t >> 6;                          // slice group 0..3

    const unsigned int* p = g_part + (size_t)(g * 8) * NPIX + px;
    unsigned int acc = p[0];
#pragma unroll
    for (int s = 1; s < 8; s++)
        acc = min(acc, p[(size_t)s * NPIX]);

    smem[t] = acc;
    __syncthreads();

    if (t < 64) {
        unsigned int a = min(min(smem[t], smem[t + 64]),
                             min(smem[t + 128], smem[t + 192]));
        out[px] = fminf(__uint_as_float(a), 100.0f);
    }
}

extern "C" void kernel_launch(void* const* d_in, const int* in_sizes, int n_in,
                              void* d_out, int out_size)
{
    const float* verts = (const float*)d_in[0];
    const int* faces = (const int*)d_in[1];
    float* out = (float*)d_out;

    dim3 grid(OW / 32, OH / 32, NB * NSLICE);   // (4, 4, 128) = 2048 CTAs
    raster_kernel<<<grid, 256>>>(verts, faces);

    finalize_kernel<<<NPIX / 64, 256>>>(out);   // 1024 CTAs
}